// round 14
// baseline (speedup 1.0000x reference)
#include <cuda_runtime.h>
#include <cstdint>

// Problem constants
#define B_   4
#define H_   384
#define W_   1280
#define GH_  192                 // int(0.5 * 384)
#define N_   (GH_ * W_)          // 245760 ground points per batch
#define HW_  (H_ * W_)           // 491520
#define HYP  25                  // MAX_IT
#define NPTS 5
#define TOLF 0.1f

// k_fit: grid (80, 4) x 256 threads, 3 float4/thread -> 80*256*3 = N_/4 exact
#define GA_X  80
#define TA    256
#define FPT_A 3
// k_dist: grid (120, 4) x 256 threads, 4 float4/thread -> 120*256*4 = HW_/4 exact
#define GB_X  120
#define TB    256
#define FPT_B 4

// Scratch (no cudaMalloc; zero-initialized; k_dist's ticket resets g_cnt/g_ack
// every run so graph replays are deterministic)
__device__ float        g_ws[B_ * HYP * 3];
__device__ int          g_cnt[B_ * HYP];
__device__ unsigned int g_ack[B_];

// ---------------------------------------------------------------------------
// Packed f32x2 helpers (sm_103a). Per-lane rounding identical to scalar
// FFMA/FADD (rn), so counts are bit-identical to the scalar formulation.
// ---------------------------------------------------------------------------
__device__ __forceinline__ void fma2(float& d0, float& d1,
                                     float a0, float a1,
                                     float b0, float b1,
                                     float c0, float c1) {
    asm("{\n\t.reg .b64 A,B,C,D;\n\t"
        "mov.b64 A,{%2,%3};\n\t"
        "mov.b64 B,{%4,%5};\n\t"
        "mov.b64 C,{%6,%7};\n\t"
        "fma.rn.f32x2 D,A,B,C;\n\t"
        "mov.b64 {%0,%1},D;\n\t}"
        : "=f"(d0), "=f"(d1)
        : "f"(a0), "f"(a1), "f"(b0), "f"(b1), "f"(c0), "f"(c1));
}
__device__ __forceinline__ void add2(float& d0, float& d1,
                                     float a0, float a1,
                                     float b0, float b1) {
    asm("{\n\t.reg .b64 A,B,D;\n\t"
        "mov.b64 A,{%2,%3};\n\t"
        "mov.b64 B,{%4,%5};\n\t"
        "add.rn.f32x2 D,A,B;\n\t"
        "mov.b64 {%0,%1},D;\n\t}"
        : "=f"(d0), "=f"(d1)
        : "f"(a0), "f"(a1), "f"(b0), "f"(b1));
}

// ---------------------------------------------------------------------------
// Kernel A: solve + count. NO block barrier before counting:
//  - each thread issues its 9 bulk LDG.128 (x, y, z; y stored negated)
//  - each WARP (lane<25) redundantly gathers 125 samples (L2-hot) and solves
//    all 25 fp64 LS systems in registers; block (0,b) warp 0 publishes g_ws
//  - count loop: packed f32x2 math (identical order: fma(x,w0,fma(z,w1,w2))
//    + (-y)), w broadcast via shfl from lane k
//  - one __syncthreads, smem merge, one global atomic per (block, hyp)
// M = A^T A + 1e-6 on EVERY entry (matches jnp broadcast).
// ---------------------------------------------------------------------------
__global__ void __launch_bounds__(TA) k_fit(const float* __restrict__ pts,
                                            const int* __restrict__ rind) {
    const int b    = blockIdx.y;
    const int tid  = threadIdx.x;
    const int lane = tid & 31;

    const float* gb = pts + (size_t)b * 3 * HW_ + (size_t)(H_ - GH_) * W_;
    const float4* xs = (const float4*)gb;
    const float4* ys = xs + (HW_ / 4);
    const float4* zs = xs + 2 * (HW_ / 4);

    // Bulk loads first: 9 independent LDG.128 per thread (in flight below)
    const int v0 = blockIdx.x * (TA * FPT_A) + tid;
    float4 X[FPT_A], nY[FPT_A], Z[FPT_A];
#pragma unroll
    for (int i = 0; i < FPT_A; i++) {
        X[i] = xs[v0 + i * TA];
        Z[i] = zs[v0 + i * TA];
        float4 y = ys[v0 + i * TA];
        nY[i] = make_float4(-y.x, -y.y, -y.z, -y.w);
    }

    // Per-warp redundant gather + fp64 solve (lane = hypothesis)
    float w0l = 0.f, w1l = 0.f, w2l = 0.f;
    if (lane < HYP) {
        const int* rb = rind + b * (HYP * NPTS) + lane * NPTS;
        int n0 = __ldg(rb + 0), n1 = __ldg(rb + 1), n2 = __ldg(rb + 2),
            n3 = __ldg(rb + 3), n4 = __ldg(rb + 4);
        double x0 = __ldg(gb + n0), x1 = __ldg(gb + n1), x2 = __ldg(gb + n2),
               x3 = __ldg(gb + n3), x4 = __ldg(gb + n4);
        double y0 = __ldg(gb + HW_ + n0), y1 = __ldg(gb + HW_ + n1),
               y2 = __ldg(gb + HW_ + n2), y3 = __ldg(gb + HW_ + n3),
               y4 = __ldg(gb + HW_ + n4);
        double z0 = __ldg(gb + 2 * HW_ + n0), z1 = __ldg(gb + 2 * HW_ + n1),
               z2 = __ldg(gb + 2 * HW_ + n2), z3 = __ldg(gb + 2 * HW_ + n3),
               z4 = __ldg(gb + 2 * HW_ + n4);

        #define PW(e0,e1,e2,e3,e4) (((e0)+(e1)) + (((e2)+(e3)) + (e4)))
        double Sxx = PW(x0*x0, x1*x1, x2*x2, x3*x3, x4*x4);
        double Sxz = PW(x0*z0, x1*z1, x2*z2, x3*z3, x4*z4);
        double Sx  = PW(x0, x1, x2, x3, x4);
        double Szz = PW(z0*z0, z1*z1, z2*z2, z3*z3, z4*z4);
        double Sz  = PW(z0, z1, z2, z3, z4);
        double Sxy = PW(x0*y0, x1*y1, x2*y2, x3*y3, x4*y4);
        double Szy = PW(z0*y0, z1*y1, z2*y2, z3*y3, z4*y4);
        double Sy  = PW(y0, y1, y2, y3, y4);
        #undef PW

        const double e = 1e-6;
        double a  = Sxx + e, bb = Sxz + e, c = Sx + e;
        double d  = Szz + e, f  = Sz  + e;
        double g  = (double)NPTS + e;

        double A00 = d * g - f * f;
        double A01 = c * f - bb * g;
        double A02 = bb * f - c * d;
        double A11 = a * g - c * c;
        double A12 = bb * c - a * f;
        double A22 = a * d - bb * bb;
        double det = (a * A00 + bb * A01) + c * A02;

        // fp32-seeded Newton reciprocal (~2^-46 rel err; outputs are fp32)
        double inv = (double)__frcp_rn((float)det);
        inv = inv * (2.0 - det * inv);
        inv = inv * (2.0 - det * inv);

        double r0 = Sxy, r1 = Szy, r2 = Sy;
        w0l = (float)(((A00 * r0 + A01 * r1) + A02 * r2) * inv);
        w1l = (float)(((A01 * r0 + A11 * r1) + A12 * r2) * inv);
        w2l = (float)(((A02 * r0 + A12 * r1) + A22 * r2) * inv);

        // block (0,b) warp 0 publishes ws for k_dist's argmax
        if (blockIdx.x == 0 && tid < HYP) {
            g_ws[(b * HYP + tid) * 3 + 0] = w0l;
            g_ws[(b * HYP + tid) * 3 + 1] = w1l;
            g_ws[(b * HYP + tid) * 3 + 2] = w2l;
        }
    }

    __shared__ int s_c[HYP];
    if (tid < HYP) s_c[tid] = 0;
    // NOTE: s_c visible before use via the __syncthreads below? No — counts
    // are accumulated AFTER the loop into s_c, guarded by the sync before the
    // atomics. Warps only touch s_c after __syncthreads.

    // Count: packed f32x2, 12 points x 25 hyps; w broadcast from lane k
    int cnt[1];
    int c_all[HYP];
#pragma unroll
    for (int k = 0; k < HYP; k++) {
        float w0 = __shfl_sync(0xffffffffu, w0l, k);
        float w1 = __shfl_sync(0xffffffffu, w1l, k);
        float w2 = __shfl_sync(0xffffffffu, w2l, k);
        int c = 0;
#pragma unroll
        for (int i = 0; i < FPT_A; i++) {
            float t0, t1;
            // pair (x, y components of the float4)
            fma2(t0, t1, Z[i].x, Z[i].y, w1, w1, w2, w2);
            fma2(t0, t1, X[i].x, X[i].y, w0, w0, t0, t1);
            add2(t0, t1, t0, t1, nY[i].x, nY[i].y);
            c += (fabsf(t0) < TOLF);
            c += (fabsf(t1) < TOLF);
            // pair (z, w components)
            fma2(t0, t1, Z[i].z, Z[i].w, w1, w1, w2, w2);
            fma2(t0, t1, X[i].z, X[i].w, w0, w0, t0, t1);
            add2(t0, t1, t0, t1, nY[i].z, nY[i].w);
            c += (fabsf(t0) < TOLF);
            c += (fabsf(t1) < TOLF);
        }
        c_all[k] = (int)__reduce_add_sync(0xffffffffu, (unsigned)c);
    }
    (void)cnt;

    __syncthreads();          // s_c zero-init visible
    if (lane == 0) {
#pragma unroll
        for (int k = 0; k < HYP; k++) atomicAdd(&s_c[k], c_all[k]);
    }
    __syncthreads();
    if (tid < HYP) atomicAdd(&g_cnt[b * HYP + tid], s_c[tid]);
}

// ---------------------------------------------------------------------------
// Kernel B: argmax + signed distance (plain stream order after k_fit — no
// PDL race). Every block: issue 12 LDG.128, load g_cnt/g_ws to smem, compute
// the first-max argmax (= jnp.argmax), dist, store. Last block per batch
// (ack ticket) resets g_cnt/g_ack for the next graph replay.
// ---------------------------------------------------------------------------
__global__ void __launch_bounds__(TB) k_dist(const float* __restrict__ pts,
                                             float* __restrict__ out,
                                             float* __restrict__ out_bw) {
    const int b   = blockIdx.y;
    const int tid = threadIdx.x;

    const float4* xs = (const float4*)(pts + (size_t)b * 3 * HW_);
    const float4* ys = xs + (HW_ / 4);
    const float4* zs = xs + 2 * (HW_ / 4);
    float4* o = (float4*)(out + (size_t)b * HW_);

    const int v0 = blockIdx.x * (TB * FPT_B) + tid;
    float4 X[FPT_B], Y[FPT_B], Z[FPT_B];
#pragma unroll
    for (int i = 0; i < FPT_B; i++) {
        X[i] = xs[v0 + i * TB];
        Y[i] = ys[v0 + i * TB];
        Z[i] = zs[v0 + i * TB];
    }

    __shared__ int   s_c[HYP];
    __shared__ float s_w[HYP * 3];
    if (tid < HYP)     s_c[tid] = __ldcg(&g_cnt[b * HYP + tid]);
    if (tid < HYP * 3) s_w[tid] = __ldcg(&g_ws[b * HYP * 3 + tid]);
    __syncthreads();

    int best = 0, bc = s_c[0];
#pragma unroll
    for (int it = 1; it < HYP; it++) {
        int v = s_c[it];
        if (v > bc) { bc = v; best = it; }   // first-max = jnp.argmax
    }
    float w0 = s_w[best * 3 + 0];
    float w1 = s_w[best * 3 + 1];
    float w2 = s_w[best * 3 + 2];

    if (blockIdx.x == 0 && tid < 3) out_bw[b * 3 + tid] = s_w[best * 3 + tid];

#pragma unroll
    for (int i = 0; i < FPT_B; i++) {
        float4 r;
        r.x = fmaf(X[i].x, w0, fmaf(Z[i].x, w1, w2)) - Y[i].x;
        r.y = fmaf(X[i].y, w0, fmaf(Z[i].y, w1, w2)) - Y[i].y;
        r.z = fmaf(X[i].z, w0, fmaf(Z[i].z, w1, w2)) - Y[i].z;
        r.w = fmaf(X[i].w, w0, fmaf(Z[i].w, w1, w2)) - Y[i].w;
        o[v0 + i * TB] = r;
    }

    // Ack ticket: this block has finished reading g_cnt (the smem load above,
    // ordered by the __syncthreads). Last block per batch resets for replay.
    if (tid == 0) {
        unsigned a = atomicAdd(&g_ack[b], 1u);
        if (a == GB_X - 1) {
#pragma unroll
            for (int it = 0; it < HYP; it++) g_cnt[b * HYP + it] = 0;
            g_ack[b] = 0;
        }
    }
}

// ---------------------------------------------------------------------------
// Launch: 2 kernels, plain stream order (race-free), graph-capturable.
// Output layout: dist (B*H*W floats) followed by best_w (B*3 floats).
// ---------------------------------------------------------------------------
extern "C" void kernel_launch(void* const* d_in, const int* in_sizes, int n_in,
                              void* d_out, int out_size) {
    const float* pts  = (const float*)d_in[0];
    const int*   rind = (const int*)d_in[1];
    float*       out  = (float*)d_out;

    k_fit<<<dim3(GA_X, B_), TA>>>(pts, rind);
    k_dist<<<dim3(GB_X, B_), TB>>>(pts, out, out + (size_t)B_ * HW_);
}

// round 15
// speedup vs baseline: 1.5333x; 1.5333x over previous
#include <cuda_runtime.h>
#include <cstdint>

// Problem constants
#define B_   4
#define H_   384
#define W_   1280
#define GH_  192                 // int(0.5 * 384)
#define N_   (GH_ * W_)          // 245760 ground points per batch
#define HW_  (H_ * W_)           // 491520
#define HYP  25                  // MAX_IT
#define NPTS 5
#define TOLF 0.1f

// k_fit: grid (80, 4) x 256 threads, 3 float4/thread -> 80*256*3 = N_/4 exact
#define GA_X  80
#define TA    256
#define FPT_A 3
// k_dist: grid (120, 4) x 256 threads, 4 float4/thread -> 120*256*4 = HW_/4 exact
#define GB_X  120
#define TB    256
#define FPT_B 4

// Scratch (no cudaMalloc; zero-initialized; k_fit's ticket resets g_cnt/g_done
// every run so graph replays are deterministic)
__device__ int          g_cnt[B_ * HYP];
__device__ unsigned int g_done[B_];
__device__ float        g_best[B_ * 3];

// ---------------------------------------------------------------------------
// Packed f32x2 helpers (sm_103a). Per-lane rn rounding identical to scalar
// FFMA/FADD, so inlier counts are bit-identical to the scalar formulation.
// ---------------------------------------------------------------------------
__device__ __forceinline__ void fma2(float& d0, float& d1,
                                     float a0, float a1,
                                     float b0, float b1,
                                     float c0, float c1) {
    asm("{\n\t.reg .b64 A,B,C,D;\n\t"
        "mov.b64 A,{%2,%3};\n\t"
        "mov.b64 B,{%4,%5};\n\t"
        "mov.b64 C,{%6,%7};\n\t"
        "fma.rn.f32x2 D,A,B,C;\n\t"
        "mov.b64 {%0,%1},D;\n\t}"
        : "=f"(d0), "=f"(d1)
        : "f"(a0), "f"(a1), "f"(b0), "f"(b1), "f"(c0), "f"(c1));
}
__device__ __forceinline__ void add2(float& d0, float& d1,
                                     float a0, float a1,
                                     float b0, float b1) {
    asm("{\n\t.reg .b64 A,B,D;\n\t"
        "mov.b64 A,{%2,%3};\n\t"
        "mov.b64 B,{%4,%5};\n\t"
        "add.rn.f32x2 D,A,B;\n\t"
        "mov.b64 {%0,%1},D;\n\t}"
        : "=f"(d0), "=f"(d1)
        : "f"(a0), "f"(a1), "f"(b0), "f"(b1));
}

// ---------------------------------------------------------------------------
// Kernel A: fused solve + count + argmax (R9 structure).
//  - each thread issues its 9 bulk LDG.128 first (y stored negated)
//  - each BLOCK gathers the batch's 125 samples (L2-hot after first wave);
//    threads 0..24 solve the 25 fp64 LS systems -> smem
//  - count: packed f32x2, 12 points x 25 hyps per thread, warp redux ->
//    smem -> one global atomic per (block, hyp)
//  - ticket: last block per batch does first-max argmax (= jnp.argmax),
//    writes g_best + out_bw, resets g_cnt/g_done for the next replay
//  - PDL trigger at the VERY END of every block: cudaGridDependencySynchronize
//    in k_dist then provably sees g_best (no scheduling race).
// M = A^T A + 1e-6 on EVERY entry (matches jnp broadcast).
// ---------------------------------------------------------------------------
__global__ void __launch_bounds__(TA) k_fit(const float* __restrict__ pts,
                                            const int* __restrict__ rind,
                                            float* __restrict__ out_bw) {
    const int b   = blockIdx.y;
    const int tid = threadIdx.x;

    const float* gb = pts + (size_t)b * 3 * HW_ + (size_t)(H_ - GH_) * W_;
    const float4* xs = (const float4*)gb;
    const float4* ys = xs + (HW_ / 4);
    const float4* zs = xs + 2 * (HW_ / 4);

    // 1) sample index load first (hides under bulk loads)
    int n = -1;
    if (tid < HYP * NPTS) n = __ldg(rind + b * (HYP * NPTS) + tid);

    // 2) bulk loads: 9 independent LDG.128 per thread
    const int v0 = blockIdx.x * (TA * FPT_A) + tid;
    float4 X[FPT_A], nY[FPT_A], Z[FPT_A];
#pragma unroll
    for (int i = 0; i < FPT_A; i++) {
        X[i] = xs[v0 + i * TA];
        Z[i] = zs[v0 + i * TA];
        float4 y = ys[v0 + i * TA];
        nY[i] = make_float4(-y.x, -y.y, -y.z, -y.w);
    }

    __shared__ float sx[HYP * NPTS], sy[HYP * NPTS], sz[HYP * NPTS];
    __shared__ float s_w[HYP * 3];
    __shared__ int   s_c[HYP];

    // 3) dependent sample gathers (rind already in flight)
    if (tid < HYP * NPTS) {
        sx[tid] = __ldg(gb + n);
        sy[tid] = __ldg(gb + HW_ + n);
        sz[tid] = __ldg(gb + 2 * HW_ + n);
    }
    if (tid < HYP) s_c[tid] = 0;
    __syncthreads();

    // 4) solve (threads 0..24, one hypothesis each, fp64, short chain)
    if (tid < HYP) {
        int o = tid * NPTS;
        double x0 = sx[o], x1 = sx[o+1], x2 = sx[o+2], x3 = sx[o+3], x4 = sx[o+4];
        double y0 = sy[o], y1 = sy[o+1], y2 = sy[o+2], y3 = sy[o+3], y4 = sy[o+4];
        double z0 = sz[o], z1 = sz[o+1], z2 = sz[o+2], z3 = sz[o+3], z4 = sz[o+4];

        #define PW(e0,e1,e2,e3,e4) (((e0)+(e1)) + (((e2)+(e3)) + (e4)))
        double Sxx = PW(x0*x0, x1*x1, x2*x2, x3*x3, x4*x4);
        double Sxz = PW(x0*z0, x1*z1, x2*z2, x3*z3, x4*z4);
        double Sx  = PW(x0, x1, x2, x3, x4);
        double Szz = PW(z0*z0, z1*z1, z2*z2, z3*z3, z4*z4);
        double Sz  = PW(z0, z1, z2, z3, z4);
        double Sxy = PW(x0*y0, x1*y1, x2*y2, x3*y3, x4*y4);
        double Szy = PW(z0*y0, z1*y1, z2*y2, z3*y3, z4*y4);
        double Sy  = PW(y0, y1, y2, y3, y4);
        #undef PW

        const double e = 1e-6;
        double a  = Sxx + e, bb = Sxz + e, c = Sx + e;
        double d  = Szz + e, f  = Sz  + e;
        double g  = (double)NPTS + e;

        double A00 = d * g - f * f;
        double A01 = c * f - bb * g;
        double A02 = bb * f - c * d;
        double A11 = a * g - c * c;
        double A12 = bb * c - a * f;
        double A22 = a * d - bb * bb;
        double det = (a * A00 + bb * A01) + c * A02;

        // fp32-seeded Newton reciprocal (~2^-46 rel err; outputs are fp32)
        double inv = (double)__frcp_rn((float)det);
        inv = inv * (2.0 - det * inv);
        inv = inv * (2.0 - det * inv);

        double r0 = Sxy, r1 = Szy, r2 = Sy;
        s_w[tid * 3 + 0] = (float)(((A00 * r0 + A01 * r1) + A02 * r2) * inv);
        s_w[tid * 3 + 1] = (float)(((A01 * r0 + A11 * r1) + A12 * r2) * inv);
        s_w[tid * 3 + 2] = (float)(((A02 * r0 + A12 * r1) + A22 * r2) * inv);
    }
    __syncthreads();

    // 5) count: packed f32x2, 12 points x 25 hypotheses per thread
    for (int k = 0; k < HYP; k++) {
        float w0 = s_w[3 * k], w1 = s_w[3 * k + 1], w2 = s_w[3 * k + 2];
        int c = 0;
#pragma unroll
        for (int i = 0; i < FPT_A; i++) {
            float t0, t1, u0, u1;
            fma2(t0, t1, Z[i].x, Z[i].y, w1, w1, w2, w2);
            fma2(u0, u1, Z[i].z, Z[i].w, w1, w1, w2, w2);
            fma2(t0, t1, X[i].x, X[i].y, w0, w0, t0, t1);
            fma2(u0, u1, X[i].z, X[i].w, w0, w0, u0, u1);
            add2(t0, t1, t0, t1, nY[i].x, nY[i].y);
            add2(u0, u1, u0, u1, nY[i].z, nY[i].w);
            c += (fabsf(t0) < TOLF);
            c += (fabsf(t1) < TOLF);
            c += (fabsf(u0) < TOLF);
            c += (fabsf(u1) < TOLF);
        }
        unsigned s = __reduce_add_sync(0xffffffffu, (unsigned)c);
        if ((tid & 31) == 0) atomicAdd(&s_c[k], (int)s);
    }
    __syncthreads();
    if (tid < HYP) atomicAdd(&g_cnt[b * HYP + tid], s_c[tid]);
    __syncthreads();

    // 6) ticket: last block per batch -> argmax + reset (deterministic replays)
    if (tid == 0) {
        __threadfence();
        unsigned old = atomicAdd(&g_done[b], 1u);
        if (old == GA_X - 1) {
            __threadfence();
            int best = 0, bc = __ldcg(&g_cnt[b * HYP]);
#pragma unroll
            for (int it = 1; it < HYP; it++) {
                int v = __ldcg(&g_cnt[b * HYP + it]);
                if (v > bc) { bc = v; best = it; }   // first-max = jnp.argmax
            }
            float bw0 = s_w[best * 3 + 0];
            float bw1 = s_w[best * 3 + 1];
            float bw2 = s_w[best * 3 + 2];
            g_best[b * 3 + 0] = bw0;
            g_best[b * 3 + 1] = bw1;
            g_best[b * 3 + 2] = bw2;
            out_bw[b * 3 + 0] = bw0;
            out_bw[b * 3 + 1] = bw1;
            out_bw[b * 3 + 2] = bw2;
            // reset for next graph replay
#pragma unroll
            for (int it = 0; it < HYP; it++) g_cnt[b * HYP + it] = 0;
            g_done[b] = 0;
            __threadfence();
        }
    }
    __syncthreads();

    // 7) PDL trigger at the very end: all prior writes (incl. the ticket
    // block's g_best) are ordered before k_dist's dependency-sync returns.
    cudaTriggerProgrammaticLaunchCompletion();
}

// ---------------------------------------------------------------------------
// Kernel B: signed distance over ALL points. PDL-dependent: issue all 12
// LDG.128 first (overlap k_fit's tail), then grid-dependency-sync (g_best
// now guaranteed visible), then compute + store.
// ---------------------------------------------------------------------------
__global__ void __launch_bounds__(TB) k_dist(const float* __restrict__ pts,
                                             float* __restrict__ out) {
    const int b   = blockIdx.y;
    const int tid = threadIdx.x;

    const float4* xs = (const float4*)(pts + (size_t)b * 3 * HW_);
    const float4* ys = xs + (HW_ / 4);
    const float4* zs = xs + 2 * (HW_ / 4);
    float4* o = (float4*)(out + (size_t)b * HW_);

    const int v0 = blockIdx.x * (TB * FPT_B) + tid;
    float4 X[FPT_B], Y[FPT_B], Z[FPT_B];
#pragma unroll
    for (int i = 0; i < FPT_B; i++) {
        X[i] = xs[v0 + i * TB];
        Y[i] = ys[v0 + i * TB];
        Z[i] = zs[v0 + i * TB];
    }

    cudaGridDependencySynchronize();   // k_fit fully done: g_best visible

    float w0 = g_best[b * 3 + 0];
    float w1 = g_best[b * 3 + 1];
    float w2 = g_best[b * 3 + 2];

#pragma unroll
    for (int i = 0; i < FPT_B; i++) {
        float4 r;
        r.x = fmaf(X[i].x, w0, fmaf(Z[i].x, w1, w2)) - Y[i].x;
        r.y = fmaf(X[i].y, w0, fmaf(Z[i].y, w1, w2)) - Y[i].y;
        r.z = fmaf(X[i].z, w0, fmaf(Z[i].z, w1, w2)) - Y[i].z;
        r.w = fmaf(X[i].w, w0, fmaf(Z[i].w, w1, w2)) - Y[i].w;
        o[v0 + i * TB] = r;
    }
}

// ---------------------------------------------------------------------------
// Launch: 2 kernels, PDL-chained (race-free: trigger at end of k_fit blocks),
// graph-capturable (no syncs, no allocs).
// Output layout: dist (B*H*W floats) followed by best_w (B*3 floats).
// ---------------------------------------------------------------------------
extern "C" void kernel_launch(void* const* d_in, const int* in_sizes, int n_in,
                              void* d_out, int out_size) {
    const float* pts  = (const float*)d_in[0];
    const int*   rind = (const int*)d_in[1];
    float*       out  = (float*)d_out;

    k_fit<<<dim3(GA_X, B_), TA>>>(pts, rind, out + (size_t)B_ * HW_);

    cudaLaunchAttribute pdl[1];
    pdl[0].id = cudaLaunchAttributeProgrammaticStreamSerialization;
    pdl[0].val.programmaticStreamSerializationAllowed = 1;

    cudaLaunchConfig_t cfg = {};
    cfg.gridDim  = dim3(GB_X, B_);
    cfg.blockDim = dim3(TB);
    cfg.attrs = pdl;
    cfg.numAttrs = 1;
    cudaLaunchKernelEx(&cfg, k_dist, pts, out);
}